// round 12
// baseline (speedup 1.0000x reference)
#include <cuda_runtime.h>

// Capsule dynamic routing. B=64, N=4096, I=8, C=32, D=16, 3 routing iters.
// NO weight prepass: both pass kernels cp.async raw W[c][n][j][i] rows into
// padded smem (row 65 f4 -> conflict-free 4-phase LDS.128 at lane=c) and use
// fma.rn.f32x2 over INPUT-dim pairs (raw layout is already pair-packed), with
// one hadd2 per (bi,j). acc/o/logit stay in j-pair u64 space.
// caps_pass0: uniform coupling; 8 b/thread, 64 b/CTA, 32 n/CTA, grid 128.
// caps_pass12: 4 b/thread, 32 b + 64 n/CTA, grid (64,2); o hoisted to regs;
//   softmax = 5-shfl butterfly over c (lane = c).
// caps_reduce: 256 CTAs, 8-way chunk split + shfl merge + squash.

#define B_ 64
#define N_ 4096
#define C_ 32

using u64 = unsigned long long;

__device__ float g_part[(size_t)128 * B_ * C_ * 16];     // 16MB partials
__device__ float g_Ocum[B_ * C_ * 16];                   // cumulative outs

__device__ __forceinline__ u64 fma2(u64 a, u64 b, u64 c) {
    u64 d; asm("fma.rn.f32x2 %0,%1,%2,%3;" : "=l"(d) : "l"(a), "l"(b), "l"(c)); return d;
}
__device__ __forceinline__ u64 mul2(u64 a, u64 b) {
    u64 d; asm("mul.rn.f32x2 %0,%1,%2;" : "=l"(d) : "l"(a), "l"(b)); return d;
}
__device__ __forceinline__ u64 add2(u64 a, u64 b) {
    u64 d; asm("add.rn.f32x2 %0,%1,%2;" : "=l"(d) : "l"(a), "l"(b)); return d;
}
__device__ __forceinline__ u64 pack2(float x) {
    u64 d; asm("mov.b64 %0,{%1,%1};" : "=l"(d) : "f"(x)); return d;
}
__device__ __forceinline__ u64 pack2f(float lo, float hi) {
    u64 d; asm("mov.b64 %0,{%1,%2};" : "=l"(d) : "f"(lo), "f"(hi)); return d;
}
__device__ __forceinline__ float hadd2(u64 v) {
    float a, b; asm("mov.b64 {%0,%1},%2;" : "=f"(a), "=f"(b) : "l"(v)); return a + b;
}
__device__ __forceinline__ float2 unpk(u64 v) {
    float a, b; asm("mov.b64 {%0,%1},%2;" : "=f"(a), "=f"(b) : "l"(v)); return make_float2(a, b);
}
__device__ __forceinline__ unsigned smem_u32(const void* p) {
    unsigned a; asm("{ .reg .u64 t; cvta.to.shared.u64 t, %1; cvt.u32.u64 %0, t; }" : "=r"(a) : "l"(p));
    return a;
}
__device__ __forceinline__ void cpa16(unsigned dst, const void* src) {
    asm volatile("cp.async.cg.shared.global [%0], [%1], 16;" :: "r"(dst), "l"(src));
}
__device__ __forceinline__ void cpa_commit() { asm volatile("cp.async.commit_group;"); }
__device__ __forceinline__ void cpa_wait1() { asm volatile("cp.async.wait_group 1;"); }
__device__ __forceinline__ void cpa_wait0() { asm volatile("cp.async.wait_group 0;"); }

// smem W layout per staged n: row c = 65 f4 (64 used: slot j*2+ip), base padded.
// 2 buffers x 2 n: f4 idx = buf*4160 + ln*2080 + c*65 + (j*2+ip).
#define SW_F4 8320                     // total sW f4 (133120 B)
#define SW_BYTES (SW_F4 * 16)

// dummy launch so ncu -s 5 captures pass12 #2
__global__ void nop_k() {}

// ---------------- pass 0: uniform coupling, 8 b/thread ----------------
// grid 128 (32 n each), 256 thr. smem: sW 130KB + sX 64KB.
__global__ void __launch_bounds__(256, 1)
caps_pass0(const float* __restrict__ X, const float* __restrict__ Wg) {
    extern __shared__ char smraw[];
    float4* sW = reinterpret_cast<float4*>(smraw);
    float4* sX = reinterpret_cast<float4*>(smraw + SW_BYTES);    // [bl 64][n 32][ih 2]
    const int chunk = blockIdx.x, n0 = chunk * 32;
    const int tid = threadIdx.x, c = tid & 31, w = tid >> 5;
    const unsigned sWa = smem_u32(sW);
    const int s_ln = tid >> 7, s_c = (tid >> 2) & 31, s_g = tid & 3;

    // stage X plain (no duplication)
    for (int t = tid; t < 64 * 32 * 2; t += 256) {
        int bl = t >> 6, rem = t & 63;
        sX[bl * 64 + rem] =
            reinterpret_cast<const float4*>(X)[(size_t)bl * 8192 + n0 * 2 + rem];
    }

    u64 acc[8][8];
    #pragma unroll
    for (int bi = 0; bi < 8; ++bi)
        #pragma unroll
        for (int q = 0; q < 8; ++q) acc[bi][q] = 0ull;

    auto stage = [&](int sub, int buf) {                // 2 n raw W rows
        const int n = n0 + sub * 2 + s_ln;
        const float4* src = reinterpret_cast<const float4*>(Wg)
                              + ((size_t)s_c * N_ + n) * 32 + s_g * 8;
        unsigned dst = sWa + (unsigned)(buf * 4160 + s_ln * 2080 + s_c * 65 + s_g * 8) * 16;
        #pragma unroll
        for (int k = 0; k < 8; ++k) cpa16(dst + k * 16, src + k);
        cpa_commit();
    };
    stage(0, 0);

    const ulonglong2* X2 = reinterpret_cast<const ulonglong2*>(sX);
    for (int sub = 0; sub < 16; ++sub) {
        if (sub < 15) { stage(sub + 1, (sub + 1) & 1); cpa_wait1(); }
        else cpa_wait0();
        __syncthreads();
        #pragma unroll
        for (int ln = 0; ln < 2; ++ln) {
            const ulonglong2* W2 = reinterpret_cast<const ulonglong2*>(
                sW + (sub & 1) * 4160 + ln * 2080) + c * 65;
            const int nloc = sub * 2 + ln;
            // hoist x for all 8 bi (broadcast LDS)
            u64 x0[8], x1[8], x2[8], x3[8];
            #pragma unroll
            for (int bi = 0; bi < 8; ++bi) {
                ulonglong2 xa = X2[(w * 8 + bi) * 64 + nloc * 2];
                ulonglong2 xb = X2[(w * 8 + bi) * 64 + nloc * 2 + 1];
                x0[bi] = xa.x; x1[bi] = xa.y; x2[bi] = xb.x; x3[bi] = xb.y;
            }
            #pragma unroll
            for (int q = 0; q < 8; ++q) {
                ulonglong2 wa0 = W2[4 * q], wa1 = W2[4 * q + 1];      // j = 2q
                ulonglong2 wb0 = W2[4 * q + 2], wb1 = W2[4 * q + 3];  // j = 2q+1
                #pragma unroll
                for (int bi = 0; bi < 8; ++bi) {
                    u64 h0 = mul2(x0[bi], wa0.x);
                    h0 = fma2(x1[bi], wa0.y, h0);
                    h0 = fma2(x2[bi], wa1.x, h0);
                    h0 = fma2(x3[bi], wa1.y, h0);
                    u64 h1 = mul2(x0[bi], wb0.x);
                    h1 = fma2(x1[bi], wb0.y, h1);
                    h1 = fma2(x2[bi], wb1.x, h1);
                    h1 = fma2(x3[bi], wb1.y, h1);
                    acc[bi][q] = add2(acc[bi][q], pack2f(hadd2(h0), hadd2(h1)));
                }
            }
        }
        __syncthreads();
    }

    #pragma unroll
    for (int bi = 0; bi < 8; ++bi) {
        const int b = w * 8 + bi;
        float4* dst = reinterpret_cast<float4*>(g_part) + (((size_t)chunk * B_ + b) * C_ + c) * 4;
        #pragma unroll
        for (int qd = 0; qd < 4; ++qd) {
            float2 p0 = unpk(acc[bi][2 * qd]), p1 = unpk(acc[bi][2 * qd + 1]);
            dst[qd] = make_float4(p0.x * (1.f / 32.f), p0.y * (1.f / 32.f),
                                  p1.x * (1.f / 32.f), p1.y * (1.f / 32.f));
        }
    }
}

// ---------------- pass 1/2: routed coupling, 4 b/thread, o in regs ----------------
// grid (64 chunks, 2 b-halves), 256 thr. smem: sW 130KB + sX 64KB.
__global__ void __launch_bounds__(256, 1)
caps_pass12(const float* __restrict__ X, const float* __restrict__ Wg) {
    extern __shared__ char smraw[];
    float4* sW = reinterpret_cast<float4*>(smraw);
    float4* sX = reinterpret_cast<float4*>(smraw + SW_BYTES);    // [bl 32][n 64][ih 2]
    const int chunk = blockIdx.x, half = blockIdx.y;
    const int n0 = chunk * 64, b0 = half * 32;
    const int tid = threadIdx.x, c = tid & 31, w = tid >> 5;
    const unsigned sWa = smem_u32(sW);
    const int s_ln = tid >> 7, s_c = (tid >> 2) & 31, s_g = tid & 3;

    for (int t = tid; t < 32 * 64 * 2; t += 256) {
        int bl = t >> 7, rem = t & 127;
        sX[bl * 128 + rem] =
            reinterpret_cast<const float4*>(X)[(size_t)(b0 + bl) * 8192 + n0 * 2 + rem];
    }

    // hoist o (cumulative outs) to registers: j-pair u64, loop-invariant over n
    u64 o2[4][8];
    #pragma unroll
    for (int bi = 0; bi < 4; ++bi) {
        const int b = b0 + w * 4 + bi;
        const ulonglong2* op = reinterpret_cast<const ulonglong2*>(g_Ocum + (b * C_ + c) * 16);
        #pragma unroll
        for (int qd = 0; qd < 4; ++qd) {
            ulonglong2 u = op[qd];
            o2[bi][2 * qd] = u.x; o2[bi][2 * qd + 1] = u.y;
        }
    }

    u64 acc[4][8];
    #pragma unroll
    for (int bi = 0; bi < 4; ++bi)
        #pragma unroll
        for (int q = 0; q < 8; ++q) acc[bi][q] = 0ull;

    auto stage = [&](int sub, int buf) {
        const int n = n0 + sub * 2 + s_ln;
        const float4* src = reinterpret_cast<const float4*>(Wg)
                              + ((size_t)s_c * N_ + n) * 32 + s_g * 8;
        unsigned dst = sWa + (unsigned)(buf * 4160 + s_ln * 2080 + s_c * 65 + s_g * 8) * 16;
        #pragma unroll
        for (int k = 0; k < 8; ++k) cpa16(dst + k * 16, src + k);
        cpa_commit();
    };
    stage(0, 0);

    const ulonglong2* X2 = reinterpret_cast<const ulonglong2*>(sX);
    for (int sub = 0; sub < 32; ++sub) {
        if (sub < 31) { stage(sub + 1, (sub + 1) & 1); cpa_wait1(); }
        else cpa_wait0();
        __syncthreads();
        #pragma unroll
        for (int ln = 0; ln < 2; ++ln) {
            const ulonglong2* W2 = reinterpret_cast<const ulonglong2*>(
                sW + (sub & 1) * 4160 + ln * 2080) + c * 65;
            const int nloc = sub * 2 + ln;
            // x for 4 bi (broadcast LDS)
            u64 x0[4], x1[4], x2[4], x3[4];
            #pragma unroll
            for (int bi = 0; bi < 4; ++bi) {
                ulonglong2 xa = X2[(w * 4 + bi) * 128 + nloc * 2];
                ulonglong2 xb = X2[(w * 4 + bi) * 128 + nloc * 2 + 1];
                x0[bi] = xa.x; x1[bi] = xa.y; x2[bi] = xb.x; x3[bi] = xb.y;
            }
            u64 hp[4][8];                               // hat j-pairs
            #pragma unroll
            for (int q = 0; q < 8; ++q) {
                ulonglong2 wa0 = W2[4 * q], wa1 = W2[4 * q + 1];      // j = 2q
                ulonglong2 wb0 = W2[4 * q + 2], wb1 = W2[4 * q + 3];  // j = 2q+1
                #pragma unroll
                for (int bi = 0; bi < 4; ++bi) {
                    u64 h0 = mul2(x0[bi], wa0.x);
                    h0 = fma2(x1[bi], wa0.y, h0);
                    h0 = fma2(x2[bi], wa1.x, h0);
                    h0 = fma2(x3[bi], wa1.y, h0);
                    u64 h1 = mul2(x0[bi], wb0.x);
                    h1 = fma2(x1[bi], wb0.y, h1);
                    h1 = fma2(x2[bi], wb1.x, h1);
                    h1 = fma2(x3[bi], wb1.y, h1);
                    hp[bi][q] = pack2f(hadd2(h0), hadd2(h1));
                }
            }
            #pragma unroll
            for (int bi = 0; bi < 4; ++bi) {
                u64 lg = mul2(hp[bi][0], o2[bi][0]);
                lg = fma2(hp[bi][1], o2[bi][1], lg);
                lg = fma2(hp[bi][2], o2[bi][2], lg); lg = fma2(hp[bi][3], o2[bi][3], lg);
                lg = fma2(hp[bi][4], o2[bi][4], lg); lg = fma2(hp[bi][5], o2[bi][5], lg);
                lg = fma2(hp[bi][6], o2[bi][6], lg); lg = fma2(hp[bi][7], o2[bi][7], lg);
                const float e = __expf(hadd2(lg));   // logits O(1): no max-sub needed
                float s = e;
                s += __shfl_xor_sync(0xffffffffu, s, 1);
                s += __shfl_xor_sync(0xffffffffu, s, 2);
                s += __shfl_xor_sync(0xffffffffu, s, 4);
                s += __shfl_xor_sync(0xffffffffu, s, 8);
                s += __shfl_xor_sync(0xffffffffu, s, 16);
                const u64 cf = pack2(__fdividef(e, s));
                #pragma unroll
                for (int q = 0; q < 8; ++q)
                    acc[bi][q] = fma2(cf, hp[bi][q], acc[bi][q]);
            }
        }
        __syncthreads();
    }

    #pragma unroll
    for (int bi = 0; bi < 4; ++bi) {
        const int b = b0 + w * 4 + bi;
        float4* dst = reinterpret_cast<float4*>(g_part) + (((size_t)chunk * B_ + b) * C_ + c) * 4;
        #pragma unroll
        for (int qd = 0; qd < 4; ++qd) {
            float2 p0 = unpk(acc[bi][2 * qd]), p1 = unpk(acc[bi][2 * qd + 1]);
            dst[qd] = make_float4(p0.x, p0.y, p1.x, p1.y);
        }
    }
}

// ---------------- reduce + squash: grid 256 x 256, 8-way chunk split ----------------
__global__ void caps_reduce(float* __restrict__ out, int mode, int nch) {
    const int gt = blockIdx.x * 256 + threadIdx.x;
    const int idx4 = gt >> 3, eighth = gt & 7;
    const int kc = nch >> 3;
    float4 a = make_float4(0.f, 0.f, 0.f, 0.f);
    const float4* gp = reinterpret_cast<const float4*>(g_part) + idx4;
    #pragma unroll 8
    for (int k = 0; k < kc; ++k) {
        float4 v = gp[(size_t)(eighth * kc + k) * 8192];
        a.x += v.x; a.y += v.y; a.z += v.z; a.w += v.w;
    }
    #pragma unroll
    for (int m = 1; m <= 4; m <<= 1) {
        a.x += __shfl_xor_sync(0xffffffffu, a.x, m);
        a.y += __shfl_xor_sync(0xffffffffu, a.y, m);
        a.z += __shfl_xor_sync(0xffffffffu, a.z, m);
        a.w += __shfl_xor_sync(0xffffffffu, a.w, m);
    }
    float sq = a.x * a.x + a.y * a.y + a.z * a.z + a.w * a.w;
    sq += __shfl_xor_sync(0xffffffffu, sq, 8);
    sq += __shfl_xor_sync(0xffffffffu, sq, 16);
    const float f = sq / ((1.f + sq) * sqrtf(sq + 1e-7f));
    float4 v = make_float4(a.x * f, a.y * f, a.z * f, a.w * f);
    if (eighth == 0) {
        float4* oc = reinterpret_cast<float4*>(g_Ocum);
        if (mode == 0) {
            oc[idx4] = v;
        } else if (mode == 1) {
            float4 o = oc[idx4];
            o.x += v.x; o.y += v.y; o.z += v.z; o.w += v.w;
            oc[idx4] = o;
        } else {
            reinterpret_cast<float4*>(out)[idx4] = v;
        }
    }
}

extern "C" void kernel_launch(void* const* d_in, const int* in_sizes, int n_in,
                              void* d_out, int out_size) {
    const float* X = (const float*)d_in[0];
    const float* W = (const float*)d_in[1];
    if (n_in >= 2 && in_sizes[0] != B_ * N_ * 8) {
        X = (const float*)d_in[1];
        W = (const float*)d_in[0];
    }
    float* out = (float*)d_out;

    const int smem = SW_BYTES + 65536;   // 133120 + 65536 = 198656 B
    cudaFuncSetAttribute(caps_pass0,  cudaFuncAttributeMaxDynamicSharedMemorySize, smem);
    cudaFuncSetAttribute(caps_pass12, cudaFuncAttributeMaxDynamicSharedMemorySize, smem);

    nop_k<<<1, 32>>>();                               // keeps ncu -s5 on pass12 #2
    caps_pass0<<<128, 256, smem>>>(X, W);
    caps_reduce<<<256, 256>>>(out, 0, 128);
    caps_pass12<<<dim3(64, 2), 256, smem>>>(X, W);
    caps_reduce<<<256, 256>>>(out, 1, 64);
    caps_pass12<<<dim3(64, 2), 256, smem>>>(X, W);
    caps_reduce<<<256, 256>>>(out, 2, 64);
}

// round 13
// speedup vs baseline: 1.1329x; 1.1329x over previous
#include <cuda_runtime.h>

// Capsule dynamic routing. B=64, N=4096, I=8, C=32, D=16, 3 routing iters.
// prep_W: one-time interleave of W into g_Wil[n][r][c] (r=jp*4+i2; f4 = j-pair
//   values for i=2i2,2i2+1) enabling linear cp.async staging.
// caps_pass0: uniform coupling; 8 b/thread, all 64 b per CTA, 32 n/CTA, grid 128.
// caps_pass12: 4 b/thread, 32 b + 64 n per CTA, grid (64,2); o in SMEM (frees
//   64 regs -> no spills); hat/logit/acc in fma.rn.f32x2; softmax 5-shfl.
//   sW double-buffered at 1-n granularity (2 x 16KB) to fit sO in smem.
// caps_reduce: 256 CTAs, 8-way chunk split + shfl merge + squash.

#define B_ 64
#define N_ 4096
#define C_ 32

using u64 = unsigned long long;

__device__ float4 g_Wil[(size_t)N_ * 1024];              // 64MB interleaved W
__device__ float g_part[(size_t)128 * B_ * C_ * 16];     // 16MB partials
__device__ float g_Ocum[B_ * C_ * 16];                   // cumulative outs

__device__ __forceinline__ u64 fma2(u64 a, u64 b, u64 c) {
    u64 d; asm("fma.rn.f32x2 %0,%1,%2,%3;" : "=l"(d) : "l"(a), "l"(b), "l"(c)); return d;
}
__device__ __forceinline__ u64 mul2(u64 a, u64 b) {
    u64 d; asm("mul.rn.f32x2 %0,%1,%2;" : "=l"(d) : "l"(a), "l"(b)); return d;
}
__device__ __forceinline__ u64 pack2(float x) {
    u64 d; asm("mov.b64 %0,{%1,%1};" : "=l"(d) : "f"(x)); return d;
}
__device__ __forceinline__ float hadd2(u64 v) {
    float a, b; asm("mov.b64 {%0,%1},%2;" : "=f"(a), "=f"(b) : "l"(v)); return a + b;
}
__device__ __forceinline__ float2 unpk(u64 v) {
    float a, b; asm("mov.b64 {%0,%1},%2;" : "=f"(a), "=f"(b) : "l"(v)); return make_float2(a, b);
}
__device__ __forceinline__ unsigned smem_u32(const void* p) {
    unsigned a; asm("{ .reg .u64 t; cvta.to.shared.u64 t, %1; cvt.u32.u64 %0, t; }" : "=r"(a) : "l"(p));
    return a;
}
__device__ __forceinline__ void cpa16(unsigned dst, const void* src) {
    asm volatile("cp.async.cg.shared.global [%0], [%1], 16;" :: "r"(dst), "l"(src));
}
__device__ __forceinline__ void cpa_commit() { asm volatile("cp.async.commit_group;"); }
__device__ __forceinline__ void cpa_wait1() { asm volatile("cp.async.wait_group 1;"); }
__device__ __forceinline__ void cpa_wait0() { asm volatile("cp.async.wait_group 0;"); }

// ---------------- W interleave prepass: grid 4096 x 256 ----------------
__global__ void prep_W(const float* __restrict__ W) {
    const int tid = threadIdx.x;
    const int c = tid & 31, jp = tid >> 5;          // jp 0..7
    const int n = blockIdx.x;
    const float4* gp = reinterpret_cast<const float4*>(W)
                         + (((size_t)c * N_ + n) * 16 + 2 * jp) * 2;
    float4 A0 = gp[0], A1 = gp[1], B0 = gp[2], B1 = gp[3];  // rows j=2jp, 2jp+1
    float4* dst = g_Wil + (size_t)n * 1024 + (jp * 4) * 32 + c;
    dst[0]  = make_float4(A0.x, B0.x, A0.y, B0.y);   // i2=0
    dst[32] = make_float4(A0.z, B0.z, A0.w, B0.w);   // i2=1
    dst[64] = make_float4(A1.x, B1.x, A1.y, B1.y);   // i2=2
    dst[96] = make_float4(A1.z, B1.z, A1.w, B1.w);   // i2=3
}

// ---------------- pass 0: uniform coupling, 8 b/thread (R11-proven) ----------------
// grid 128 (chunks of 32 n), 256 thr. smem: sW 64KB (2 buf x 2 n) + sXp 128KB.
__global__ void __launch_bounds__(256, 1)
caps_pass0(const float* __restrict__ X) {
    extern __shared__ char smraw[];
    float4* sW = reinterpret_cast<float4*>(smraw);               // 4096 f4
    u64* sXp = reinterpret_cast<u64*>(smraw + 65536);            // [bl][n][i] dup pairs
    const int chunk = blockIdx.x, n0 = chunk * 32;
    const int tid = threadIdx.x, c = tid & 31, w = tid >> 5;
    const unsigned sWa = smem_u32(sW);

    for (int t = tid; t < 64 * 32 * 2; t += 256) {
        int bl = t >> 6, rem = t & 63;                           // rem = n*2+ih
        float4 v = reinterpret_cast<const float4*>(X)[(size_t)bl * 8192 + n0 * 2 + rem];
        u64* d = sXp + bl * 256 + (rem >> 1) * 8 + (rem & 1) * 4;
        d[0] = pack2(v.x); d[1] = pack2(v.y); d[2] = pack2(v.z); d[3] = pack2(v.w);
    }

    u64 acc[8][8];
    #pragma unroll
    for (int bi = 0; bi < 8; ++bi)
        #pragma unroll
        for (int q = 0; q < 8; ++q) acc[bi][q] = 0ull;

    auto stage = [&](int sub, int buf) {
        const float4* src = g_Wil + (size_t)(n0 + sub * 2) * 1024;
        unsigned dst = sWa + (unsigned)(buf * 2048 + tid) * 16;
        #pragma unroll
        for (int k = 0; k < 8; ++k) cpa16(dst + k * 4096, src + tid + k * 256);
        cpa_commit();
    };
    stage(0, 0);

    for (int sub = 0; sub < 16; ++sub) {
        if (sub < 15) { stage(sub + 1, (sub + 1) & 1); cpa_wait1(); }
        else cpa_wait0();
        __syncthreads();
        const float4* Wb = sW + (sub & 1) * 2048;
        #pragma unroll
        for (int ln = 0; ln < 2; ++ln) {
            const float4* Wn = Wb + ln * 1024;
            const int nloc = sub * 2 + ln;
            #pragma unroll
            for (int q = 0; q < 4; ++q) {
                ulonglong2 Wq[8];
                #pragma unroll
                for (int k = 0; k < 8; ++k)
                    Wq[k] = reinterpret_cast<const ulonglong2*>(Wn + (q * 8 + k) * 32)[c];
                #pragma unroll
                for (int bi = 0; bi < 8; ++bi) {
                    const ulonglong2* xp = reinterpret_cast<const ulonglong2*>(
                        sXp + (w * 8 + bi) * 256 + nloc * 8);
                    ulonglong2 xA = xp[0], xB = xp[1], xC = xp[2], xD = xp[3];
                    u64 a0 = acc[bi][2 * q], a1 = acc[bi][2 * q + 1];
                    a0 = fma2(xA.x, Wq[0].x, a0); a0 = fma2(xA.y, Wq[0].y, a0);
                    a0 = fma2(xB.x, Wq[1].x, a0); a0 = fma2(xB.y, Wq[1].y, a0);
                    a0 = fma2(xC.x, Wq[2].x, a0); a0 = fma2(xC.y, Wq[2].y, a0);
                    a0 = fma2(xD.x, Wq[3].x, a0); a0 = fma2(xD.y, Wq[3].y, a0);
                    a1 = fma2(xA.x, Wq[4].x, a1); a1 = fma2(xA.y, Wq[4].y, a1);
                    a1 = fma2(xB.x, Wq[5].x, a1); a1 = fma2(xB.y, Wq[5].y, a1);
                    a1 = fma2(xC.x, Wq[6].x, a1); a1 = fma2(xC.y, Wq[6].y, a1);
                    a1 = fma2(xD.x, Wq[7].x, a1); a1 = fma2(xD.y, Wq[7].y, a1);
                    acc[bi][2 * q] = a0; acc[bi][2 * q + 1] = a1;
                }
            }
        }
        __syncthreads();
    }

    #pragma unroll
    for (int bi = 0; bi < 8; ++bi) {
        const int b = w * 8 + bi;
        float4* dst = reinterpret_cast<float4*>(g_part) + (((size_t)chunk * B_ + b) * C_ + c) * 4;
        #pragma unroll
        for (int qd = 0; qd < 4; ++qd) {
            float2 p0 = unpk(acc[bi][2 * qd]), p1 = unpk(acc[bi][2 * qd + 1]);
            dst[qd] = make_float4(p0.x * (1.f / 32.f), p0.y * (1.f / 32.f),
                                  p1.x * (1.f / 32.f), p1.y * (1.f / 32.f));
        }
    }
}

// ---------------- pass 1/2: 4 b/thread, o in SMEM (spill relief) ----------------
// grid (64 chunks, 2 b-halves), 256 thr.
// smem: sW 32KB (2 buf x 1 n) + sXp 128KB + sO 64KB = 224KB.
// sO layout: ulonglong2 idx (bl*4 + jq)*32 + c  (lane-strided 16B, conflict-free).
__global__ void __launch_bounds__(256, 1)
caps_pass12(const float* __restrict__ X) {
    extern __shared__ char smraw[];
    float4* sW = reinterpret_cast<float4*>(smraw);               // 2048 f4 (2 x 1 n)
    u64* sXp = reinterpret_cast<u64*>(smraw + 32768);            // [bl 32][n 64][i 8]
    ulonglong2* sO = reinterpret_cast<ulonglong2*>(smraw + 32768 + 131072);
    const int chunk = blockIdx.x, half = blockIdx.y;
    const int n0 = chunk * 64, b0 = half * 32;
    const int tid = threadIdx.x, c = tid & 31, w = tid >> 5;
    const unsigned sWa = smem_u32(sW);

    for (int t = tid; t < 32 * 64 * 2; t += 256) {
        int bl = t >> 7, rem = t & 127;
        float4 v = reinterpret_cast<const float4*>(X)[(size_t)(b0 + bl) * 8192 + n0 * 2 + rem];
        u64* d = sXp + bl * 512 + (rem >> 1) * 8 + (rem & 1) * 4;
        d[0] = pack2(v.x); d[1] = pack2(v.y); d[2] = pack2(v.z); d[3] = pack2(v.w);
    }

    // stage o (cumulative outs) into smem: 4096 ulonglong2
    for (int t = tid; t < 4096; t += 256) {
        int cc = t & 31, jq = (t >> 5) & 3, bl = t >> 7;
        ulonglong2 v = reinterpret_cast<const ulonglong2*>(g_Ocum)
                           [((size_t)(b0 + bl) * C_ + cc) * 4 + jq];
        sO[(bl * 4 + jq) * 32 + cc] = v;
    }

    u64 acc[4][8];
    #pragma unroll
    for (int bi = 0; bi < 4; ++bi)
        #pragma unroll
        for (int jp = 0; jp < 8; ++jp) acc[bi][jp] = 0ull;

    auto stage = [&](int sub, int buf) {                 // 1 n = 1024 f4 = 16KB
        const float4* src = g_Wil + (size_t)(n0 + sub) * 1024;
        unsigned dst = sWa + (unsigned)(buf * 1024 + tid) * 16;
        #pragma unroll
        for (int k = 0; k < 4; ++k) cpa16(dst + k * 4096, src + tid + k * 256);
        cpa_commit();
    };
    stage(0, 0);

    for (int sub = 0; sub < 64; ++sub) {
        if (sub < 63) { stage(sub + 1, (sub + 1) & 1); cpa_wait1(); }
        else cpa_wait0();
        __syncthreads();
        const float4* Wn = sW + (sub & 1) * 1024;
        u64 hat[4][8];
        #pragma unroll
        for (int q = 0; q < 4; ++q) {
            ulonglong2 Wq[8];
            #pragma unroll
            for (int k = 0; k < 8; ++k)
                Wq[k] = reinterpret_cast<const ulonglong2*>(Wn + (q * 8 + k) * 32)[c];
            #pragma unroll
            for (int bi = 0; bi < 4; ++bi) {
                const ulonglong2* xp = reinterpret_cast<const ulonglong2*>(
                    sXp + (w * 4 + bi) * 512 + sub * 8);
                ulonglong2 xA = xp[0], xB = xp[1], xC = xp[2], xD = xp[3];
                u64 h0 = mul2(xA.x, Wq[0].x);
                h0 = fma2(xA.y, Wq[0].y, h0);
                h0 = fma2(xB.x, Wq[1].x, h0); h0 = fma2(xB.y, Wq[1].y, h0);
                h0 = fma2(xC.x, Wq[2].x, h0); h0 = fma2(xC.y, Wq[2].y, h0);
                h0 = fma2(xD.x, Wq[3].x, h0); h0 = fma2(xD.y, Wq[3].y, h0);
                u64 h1 = mul2(xA.x, Wq[4].x);
                h1 = fma2(xA.y, Wq[4].y, h1);
                h1 = fma2(xB.x, Wq[5].x, h1); h1 = fma2(xB.y, Wq[5].y, h1);
                h1 = fma2(xC.x, Wq[6].x, h1); h1 = fma2(xC.y, Wq[6].y, h1);
                h1 = fma2(xD.x, Wq[7].x, h1); h1 = fma2(xD.y, Wq[7].y, h1);
                hat[bi][2 * q] = h0; hat[bi][2 * q + 1] = h1;
            }
        }
        #pragma unroll
        for (int bi = 0; bi < 4; ++bi) {
            const ulonglong2* op = sO + ((w * 4 + bi) * 4) * 32 + c;
            ulonglong2 oq0 = op[0], oq1 = op[32], oq2 = op[64], oq3 = op[96];
            u64 lg = mul2(hat[bi][0], oq0.x);
            lg = fma2(hat[bi][1], oq0.y, lg);
            lg = fma2(hat[bi][2], oq1.x, lg); lg = fma2(hat[bi][3], oq1.y, lg);
            lg = fma2(hat[bi][4], oq2.x, lg); lg = fma2(hat[bi][5], oq2.y, lg);
            lg = fma2(hat[bi][6], oq3.x, lg); lg = fma2(hat[bi][7], oq3.y, lg);
            const float e = __expf(hadd2(lg));   // logits O(1): no max-sub needed
            float s = e;
            s += __shfl_xor_sync(0xffffffffu, s, 1);
            s += __shfl_xor_sync(0xffffffffu, s, 2);
            s += __shfl_xor_sync(0xffffffffu, s, 4);
            s += __shfl_xor_sync(0xffffffffu, s, 8);
            s += __shfl_xor_sync(0xffffffffu, s, 16);
            const u64 cf = pack2(__fdividef(e, s));
            #pragma unroll
            for (int jp = 0; jp < 8; ++jp)
                acc[bi][jp] = fma2(cf, hat[bi][jp], acc[bi][jp]);
        }
        __syncthreads();
    }

    #pragma unroll
    for (int bi = 0; bi < 4; ++bi) {
        const int b = b0 + w * 4 + bi;
        float4* dst = reinterpret_cast<float4*>(g_part) + (((size_t)chunk * B_ + b) * C_ + c) * 4;
        #pragma unroll
        for (int qd = 0; qd < 4; ++qd) {
            float2 p0 = unpk(acc[bi][2 * qd]), p1 = unpk(acc[bi][2 * qd + 1]);
            dst[qd] = make_float4(p0.x, p0.y, p1.x, p1.y);
        }
    }
}

// ---------------- reduce + squash: grid 256 x 256, 8-way chunk split ----------------
__global__ void caps_reduce(float* __restrict__ out, int mode, int nch) {
    const int gt = blockIdx.x * 256 + threadIdx.x;
    const int idx4 = gt >> 3, eighth = gt & 7;
    const int kc = nch >> 3;
    float4 a = make_float4(0.f, 0.f, 0.f, 0.f);
    const float4* gp = reinterpret_cast<const float4*>(g_part) + idx4;
    #pragma unroll 8
    for (int k = 0; k < kc; ++k) {
        float4 v = gp[(size_t)(eighth * kc + k) * 8192];
        a.x += v.x; a.y += v.y; a.z += v.z; a.w += v.w;
    }
    #pragma unroll
    for (int m = 1; m <= 4; m <<= 1) {
        a.x += __shfl_xor_sync(0xffffffffu, a.x, m);
        a.y += __shfl_xor_sync(0xffffffffu, a.y, m);
        a.z += __shfl_xor_sync(0xffffffffu, a.z, m);
        a.w += __shfl_xor_sync(0xffffffffu, a.w, m);
    }
    float sq = a.x * a.x + a.y * a.y + a.z * a.z + a.w * a.w;
    sq += __shfl_xor_sync(0xffffffffu, sq, 8);
    sq += __shfl_xor_sync(0xffffffffu, sq, 16);
    const float f = sq / ((1.f + sq) * sqrtf(sq + 1e-7f));
    float4 v = make_float4(a.x * f, a.y * f, a.z * f, a.w * f);
    if (eighth == 0) {
        float4* oc = reinterpret_cast<float4*>(g_Ocum);
        if (mode == 0) {
            oc[idx4] = v;
        } else if (mode == 1) {
            float4 o = oc[idx4];
            o.x += v.x; o.y += v.y; o.z += v.z; o.w += v.w;
            oc[idx4] = o;
        } else {
            reinterpret_cast<float4*>(out)[idx4] = v;
        }
    }
}

extern "C" void kernel_launch(void* const* d_in, const int* in_sizes, int n_in,
                              void* d_out, int out_size) {
    const float* X = (const float*)d_in[0];
    const float* W = (const float*)d_in[1];
    if (n_in >= 2 && in_sizes[0] != B_ * N_ * 8) {
        X = (const float*)d_in[1];
        W = (const float*)d_in[0];
    }
    float* out = (float*)d_out;

    const int smem0  = 65536 + 131072;              // 192KB
    const int smem12 = 32768 + 131072 + 65536;      // 224KB
    cudaFuncSetAttribute(caps_pass0,  cudaFuncAttributeMaxDynamicSharedMemorySize, smem0);
    cudaFuncSetAttribute(caps_pass12, cudaFuncAttributeMaxDynamicSharedMemorySize, smem12);

    prep_W<<<N_, 256>>>(W);
    caps_pass0<<<128, 256, smem0>>>(X);
    caps_reduce<<<256, 256>>>(out, 0, 128);
    caps_pass12<<<dim3(64, 2), 256, smem12>>>(X);
    caps_reduce<<<256, 256>>>(out, 1, 64);
    caps_pass12<<<dim3(64, 2), 256, smem12>>>(X);
    caps_reduce<<<256, 256>>>(out, 2, 64);
}

// round 14
// speedup vs baseline: 1.1865x; 1.0473x over previous
#include <cuda_runtime.h>

// Capsule dynamic routing. B=64, N=4096, I=8, C=32, D=16, 3 routing iters.
// prep_W: one-time interleave of W into g_Wil[n][r][c] (r=jp*4+i2; f4 = j-pair
//   values for i=2i2,2i2+1) enabling linear cp.async staging.
// caps_pass0: uniform coupling; 8 b/thread, 64 b/CTA; 148 CTAs x 26/28 n
//   (full-wave on 148 SMs; 2048 2n-units = 148*13 + 124).
// caps_pass12: 4 b/thread, 32 b/CTA; grid (74,2) x 54/56 n (2048 = 74*27+50);
//   o hoisted to regs; hat/logit/acc in fma.rn.f32x2; softmax 5-shfl (lane=c).
// caps_reduce: 256 CTAs, 8-way uneven chunk split + shfl merge + squash.

#define B_ 64
#define N_ 4096
#define C_ 32

using u64 = unsigned long long;

__device__ float4 g_Wil[(size_t)N_ * 1024];              // 64MB interleaved W
__device__ float g_part[(size_t)148 * B_ * C_ * 16];     // 19.4MB partials
__device__ float g_Ocum[B_ * C_ * 16];                   // cumulative outs

__device__ __forceinline__ u64 fma2(u64 a, u64 b, u64 c) {
    u64 d; asm("fma.rn.f32x2 %0,%1,%2,%3;" : "=l"(d) : "l"(a), "l"(b), "l"(c)); return d;
}
__device__ __forceinline__ u64 mul2(u64 a, u64 b) {
    u64 d; asm("mul.rn.f32x2 %0,%1,%2;" : "=l"(d) : "l"(a), "l"(b)); return d;
}
__device__ __forceinline__ u64 pack2(float x) {
    u64 d; asm("mov.b64 %0,{%1,%1};" : "=l"(d) : "f"(x)); return d;
}
__device__ __forceinline__ float hadd2(u64 v) {
    float a, b; asm("mov.b64 {%0,%1},%2;" : "=f"(a), "=f"(b) : "l"(v)); return a + b;
}
__device__ __forceinline__ float2 unpk(u64 v) {
    float a, b; asm("mov.b64 {%0,%1},%2;" : "=f"(a), "=f"(b) : "l"(v)); return make_float2(a, b);
}
__device__ __forceinline__ unsigned smem_u32(const void* p) {
    unsigned a; asm("{ .reg .u64 t; cvta.to.shared.u64 t, %1; cvt.u32.u64 %0, t; }" : "=r"(a) : "l"(p));
    return a;
}
__device__ __forceinline__ void cpa16(unsigned dst, const void* src) {
    asm volatile("cp.async.cg.shared.global [%0], [%1], 16;" :: "r"(dst), "l"(src));
}
__device__ __forceinline__ void cpa_commit() { asm volatile("cp.async.commit_group;"); }
__device__ __forceinline__ void cpa_wait1() { asm volatile("cp.async.wait_group 1;"); }
__device__ __forceinline__ void cpa_wait0() { asm volatile("cp.async.wait_group 0;"); }

// ---------------- W interleave prepass: grid 4096 x 256 ----------------
__global__ void prep_W(const float* __restrict__ W) {
    const int tid = threadIdx.x;
    const int c = tid & 31, jp = tid >> 5;          // jp 0..7
    const int n = blockIdx.x;
    const float4* gp = reinterpret_cast<const float4*>(W)
                         + (((size_t)c * N_ + n) * 16 + 2 * jp) * 2;
    float4 A0 = gp[0], A1 = gp[1], B0 = gp[2], B1 = gp[3];  // rows j=2jp, 2jp+1
    float4* dst = g_Wil + (size_t)n * 1024 + (jp * 4) * 32 + c;
    dst[0]  = make_float4(A0.x, B0.x, A0.y, B0.y);   // i2=0
    dst[32] = make_float4(A0.z, B0.z, A0.w, B0.w);   // i2=1
    dst[64] = make_float4(A1.x, B1.x, A1.y, B1.y);   // i2=2
    dst[96] = make_float4(A1.z, B1.z, A1.w, B1.w);   // i2=3
}

// ---------------- pass 0: uniform coupling, 8 b/thread, 148 CTAs ----------------
// smem: sW 64KB (2 buf x 2 n) + sXp 128KB (64 b x up to 28 n dup pairs).
__global__ void __launch_bounds__(256, 1)
caps_pass0(const float* __restrict__ X) {
    extern __shared__ char smraw[];
    float4* sW = reinterpret_cast<float4*>(smraw);               // 4096 f4
    u64* sXp = reinterpret_cast<u64*>(smraw + 65536);            // [bl][n 32][i] dup pairs
    const int chunk = blockIdx.x;
    const int count = 13 + (chunk < 124 ? 1 : 0);                // 2n-units
    const int n0 = (chunk * 13 + min(chunk, 124)) * 2;
    const int tid = threadIdx.x, c = tid & 31, w = tid >> 5;
    const unsigned sWa = smem_u32(sW);

    // stage X as duplicated pairs (guarded: rem < 4*count f4 per bl)
    const int remMax = 4 * count;                                // <= 56
    for (int t = tid; t < 64 * 64; t += 256) {
        int bl = t >> 6, rem = t & 63;                           // rem = n*2+ih
        if (rem < remMax) {
            float4 v = reinterpret_cast<const float4*>(X)[(size_t)bl * 8192 + n0 * 2 + rem];
            u64* d = sXp + bl * 256 + (rem >> 1) * 8 + (rem & 1) * 4;
            d[0] = pack2(v.x); d[1] = pack2(v.y); d[2] = pack2(v.z); d[3] = pack2(v.w);
        }
    }

    u64 acc[8][8];
    #pragma unroll
    for (int bi = 0; bi < 8; ++bi)
        #pragma unroll
        for (int q = 0; q < 8; ++q) acc[bi][q] = 0ull;

    auto stage = [&](int sub, int buf) {
        const float4* src = g_Wil + (size_t)(n0 + sub * 2) * 1024;
        unsigned dst = sWa + (unsigned)(buf * 2048 + tid) * 16;
        #pragma unroll
        for (int k = 0; k < 8; ++k) cpa16(dst + k * 4096, src + tid + k * 256);
        cpa_commit();
    };
    stage(0, 0);

    for (int sub = 0; sub < count; ++sub) {
        if (sub < count - 1) { stage(sub + 1, (sub + 1) & 1); cpa_wait1(); }
        else cpa_wait0();
        __syncthreads();
        const float4* Wb = sW + (sub & 1) * 2048;
        #pragma unroll
        for (int ln = 0; ln < 2; ++ln) {
            const float4* Wn = Wb + ln * 1024;
            const int nloc = sub * 2 + ln;
            #pragma unroll
            for (int q = 0; q < 4; ++q) {
                ulonglong2 Wq[8];
                #pragma unroll
                for (int k = 0; k < 8; ++k)
                    Wq[k] = reinterpret_cast<const ulonglong2*>(Wn + (q * 8 + k) * 32)[c];
                #pragma unroll
                for (int bi = 0; bi < 8; ++bi) {
                    const ulonglong2* xp = reinterpret_cast<const ulonglong2*>(
                        sXp + (w * 8 + bi) * 256 + nloc * 8);
                    ulonglong2 xA = xp[0], xB = xp[1], xC = xp[2], xD = xp[3];
                    u64 a0 = acc[bi][2 * q], a1 = acc[bi][2 * q + 1];
                    a0 = fma2(xA.x, Wq[0].x, a0); a0 = fma2(xA.y, Wq[0].y, a0);
                    a0 = fma2(xB.x, Wq[1].x, a0); a0 = fma2(xB.y, Wq[1].y, a0);
                    a0 = fma2(xC.x, Wq[2].x, a0); a0 = fma2(xC.y, Wq[2].y, a0);
                    a0 = fma2(xD.x, Wq[3].x, a0); a0 = fma2(xD.y, Wq[3].y, a0);
                    a1 = fma2(xA.x, Wq[4].x, a1); a1 = fma2(xA.y, Wq[4].y, a1);
                    a1 = fma2(xB.x, Wq[5].x, a1); a1 = fma2(xB.y, Wq[5].y, a1);
                    a1 = fma2(xC.x, Wq[6].x, a1); a1 = fma2(xC.y, Wq[6].y, a1);
                    a1 = fma2(xD.x, Wq[7].x, a1); a1 = fma2(xD.y, Wq[7].y, a1);
                    acc[bi][2 * q] = a0; acc[bi][2 * q + 1] = a1;
                }
            }
        }
        __syncthreads();
    }

    #pragma unroll
    for (int bi = 0; bi < 8; ++bi) {
        const int b = w * 8 + bi;
        float4* dst = reinterpret_cast<float4*>(g_part) + (((size_t)chunk * B_ + b) * C_ + c) * 4;
        #pragma unroll
        for (int qd = 0; qd < 4; ++qd) {
            float2 p0 = unpk(acc[bi][2 * qd]), p1 = unpk(acc[bi][2 * qd + 1]);
            dst[qd] = make_float4(p0.x * (1.f / 32.f), p0.y * (1.f / 32.f),
                                  p1.x * (1.f / 32.f), p1.y * (1.f / 32.f));
        }
    }
}

// ---------------- pass 1/2: 4 b/thread, o in regs, grid (74, 2) ----------------
// smem: sW 64KB + sXp 128KB (32 b x up to 56 n dup pairs).
__global__ void __launch_bounds__(256, 1)
caps_pass12(const float* __restrict__ X) {
    extern __shared__ char smraw[];
    float4* sW = reinterpret_cast<float4*>(smraw);
    u64* sXp = reinterpret_cast<u64*>(smraw + 65536);            // [bl 32][n 64][i 8]
    const int chunk = blockIdx.x, half = blockIdx.y;
    const int count = 27 + (chunk < 50 ? 1 : 0);                 // 2n-units
    const int n0 = (chunk * 27 + min(chunk, 50)) * 2;
    const int b0 = half * 32;
    const int tid = threadIdx.x, c = tid & 31, w = tid >> 5;
    const unsigned sWa = smem_u32(sW);

    const int remMax = 4 * count;                                // <= 112
    for (int t = tid; t < 32 * 128; t += 256) {
        int bl = t >> 7, rem = t & 127;
        if (rem < remMax) {
            float4 v = reinterpret_cast<const float4*>(X)[(size_t)(b0 + bl) * 8192 + n0 * 2 + rem];
            u64* d = sXp + bl * 512 + (rem >> 1) * 8 + (rem & 1) * 4;
            d[0] = pack2(v.x); d[1] = pack2(v.y); d[2] = pack2(v.z); d[3] = pack2(v.w);
        }
    }

    // hoist o (cumulative outs) to registers: loop-invariant over n
    u64 o2[4][8];
    #pragma unroll
    for (int bi = 0; bi < 4; ++bi) {
        const int b = b0 + w * 4 + bi;
        const ulonglong2* op = reinterpret_cast<const ulonglong2*>(g_Ocum + (b * C_ + c) * 16);
        #pragma unroll
        for (int qd = 0; qd < 4; ++qd) {
            ulonglong2 u = op[qd];
            o2[bi][2 * qd] = u.x; o2[bi][2 * qd + 1] = u.y;
        }
    }

    u64 acc[4][8];
    #pragma unroll
    for (int bi = 0; bi < 4; ++bi)
        #pragma unroll
        for (int jp = 0; jp < 8; ++jp) acc[bi][jp] = 0ull;

    auto stage = [&](int sub, int buf) {
        const float4* src = g_Wil + (size_t)(n0 + sub * 2) * 1024;
        unsigned dst = sWa + (unsigned)(buf * 2048 + tid) * 16;
        #pragma unroll
        for (int k = 0; k < 8; ++k) cpa16(dst + k * 4096, src + tid + k * 256);
        cpa_commit();
    };
    stage(0, 0);

    for (int sub = 0; sub < count; ++sub) {
        if (sub < count - 1) { stage(sub + 1, (sub + 1) & 1); cpa_wait1(); }
        else cpa_wait0();
        __syncthreads();
        const float4* Wb = sW + (sub & 1) * 2048;
        #pragma unroll
        for (int ln = 0; ln < 2; ++ln) {
            const float4* Wn = Wb + ln * 1024;
            const int nloc = sub * 2 + ln;
            u64 hat[4][8];
            #pragma unroll
            for (int q = 0; q < 4; ++q) {
                ulonglong2 Wq[8];
                #pragma unroll
                for (int k = 0; k < 8; ++k)
                    Wq[k] = reinterpret_cast<const ulonglong2*>(Wn + (q * 8 + k) * 32)[c];
                #pragma unroll
                for (int bi = 0; bi < 4; ++bi) {
                    const ulonglong2* xp = reinterpret_cast<const ulonglong2*>(
                        sXp + (w * 4 + bi) * 512 + nloc * 8);
                    ulonglong2 xA = xp[0], xB = xp[1], xC = xp[2], xD = xp[3];
                    u64 h0 = mul2(xA.x, Wq[0].x);
                    h0 = fma2(xA.y, Wq[0].y, h0);
                    h0 = fma2(xB.x, Wq[1].x, h0); h0 = fma2(xB.y, Wq[1].y, h0);
                    h0 = fma2(xC.x, Wq[2].x, h0); h0 = fma2(xC.y, Wq[2].y, h0);
                    h0 = fma2(xD.x, Wq[3].x, h0); h0 = fma2(xD.y, Wq[3].y, h0);
                    u64 h1 = mul2(xA.x, Wq[4].x);
                    h1 = fma2(xA.y, Wq[4].y, h1);
                    h1 = fma2(xB.x, Wq[5].x, h1); h1 = fma2(xB.y, Wq[5].y, h1);
                    h1 = fma2(xC.x, Wq[6].x, h1); h1 = fma2(xC.y, Wq[6].y, h1);
                    h1 = fma2(xD.x, Wq[7].x, h1); h1 = fma2(xD.y, Wq[7].y, h1);
                    hat[bi][2 * q] = h0; hat[bi][2 * q + 1] = h1;
                }
            }
            #pragma unroll
            for (int bi = 0; bi < 4; ++bi) {
                u64 lg = mul2(hat[bi][0], o2[bi][0]);
                lg = fma2(hat[bi][1], o2[bi][1], lg);
                lg = fma2(hat[bi][2], o2[bi][2], lg); lg = fma2(hat[bi][3], o2[bi][3], lg);
                lg = fma2(hat[bi][4], o2[bi][4], lg); lg = fma2(hat[bi][5], o2[bi][5], lg);
                lg = fma2(hat[bi][6], o2[bi][6], lg); lg = fma2(hat[bi][7], o2[bi][7], lg);
                const float e = __expf(hadd2(lg));   // logits O(1): no max-sub needed
                float s = e;
                s += __shfl_xor_sync(0xffffffffu, s, 1);
                s += __shfl_xor_sync(0xffffffffu, s, 2);
                s += __shfl_xor_sync(0xffffffffu, s, 4);
                s += __shfl_xor_sync(0xffffffffu, s, 8);
                s += __shfl_xor_sync(0xffffffffu, s, 16);
                const u64 cf = pack2(__fdividef(e, s));
                #pragma unroll
                for (int jp = 0; jp < 8; ++jp)
                    acc[bi][jp] = fma2(cf, hat[bi][jp], acc[bi][jp]);
            }
        }
        __syncthreads();
    }

    #pragma unroll
    for (int bi = 0; bi < 4; ++bi) {
        const int b = b0 + w * 4 + bi;
        float4* dst = reinterpret_cast<float4*>(g_part) + (((size_t)chunk * B_ + b) * C_ + c) * 4;
        #pragma unroll
        for (int qd = 0; qd < 4; ++qd) {
            float2 p0 = unpk(acc[bi][2 * qd]), p1 = unpk(acc[bi][2 * qd + 1]);
            dst[qd] = make_float4(p0.x, p0.y, p1.x, p1.y);
        }
    }
}

// ---------------- reduce + squash: grid 256 x 256, uneven 8-way split ----------------
__global__ void caps_reduce(float* __restrict__ out, int mode, int nch) {
    const int gt = blockIdx.x * 256 + threadIdx.x;
    const int idx4 = gt >> 3, eighth = gt & 7;
    const int kc = nch >> 3, rem = nch & 7;
    const int kstart = eighth * kc + min(eighth, rem);
    const int kcount = kc + (eighth < rem ? 1 : 0);
    float4 a = make_float4(0.f, 0.f, 0.f, 0.f);
    const float4* gp = reinterpret_cast<const float4*>(g_part) + idx4;
    for (int k = 0; k < kcount; ++k) {
        float4 v = gp[(size_t)(kstart + k) * 8192];
        a.x += v.x; a.y += v.y; a.z += v.z; a.w += v.w;
    }
    #pragma unroll
    for (int m = 1; m <= 4; m <<= 1) {
        a.x += __shfl_xor_sync(0xffffffffu, a.x, m);
        a.y += __shfl_xor_sync(0xffffffffu, a.y, m);
        a.z += __shfl_xor_sync(0xffffffffu, a.z, m);
        a.w += __shfl_xor_sync(0xffffffffu, a.w, m);
    }
    float sq = a.x * a.x + a.y * a.y + a.z * a.z + a.w * a.w;
    sq += __shfl_xor_sync(0xffffffffu, sq, 8);
    sq += __shfl_xor_sync(0xffffffffu, sq, 16);
    const float f = sq / ((1.f + sq) * sqrtf(sq + 1e-7f));
    float4 v = make_float4(a.x * f, a.y * f, a.z * f, a.w * f);
    if (eighth == 0) {
        float4* oc = reinterpret_cast<float4*>(g_Ocum);
        if (mode == 0) {
            oc[idx4] = v;
        } else if (mode == 1) {
            float4 o = oc[idx4];
            o.x += v.x; o.y += v.y; o.z += v.z; o.w += v.w;
            oc[idx4] = o;
        } else {
            reinterpret_cast<float4*>(out)[idx4] = v;
        }
    }
}

extern "C" void kernel_launch(void* const* d_in, const int* in_sizes, int n_in,
                              void* d_out, int out_size) {
    const float* X = (const float*)d_in[0];
    const float* W = (const float*)d_in[1];
    if (n_in >= 2 && in_sizes[0] != B_ * N_ * 8) {
        X = (const float*)d_in[1];
        W = (const float*)d_in[0];
    }
    float* out = (float*)d_out;

    const int smem0  = 65536 + 131072;   // 192KB
    const int smem12 = 65536 + 131072;   // 192KB
    cudaFuncSetAttribute(caps_pass0,  cudaFuncAttributeMaxDynamicSharedMemorySize, smem0);
    cudaFuncSetAttribute(caps_pass12, cudaFuncAttributeMaxDynamicSharedMemorySize, smem12);

    prep_W<<<N_, 256>>>(W);
    caps_pass0<<<148, 256, smem0>>>(X);
    caps_reduce<<<256, 256>>>(out, 0, 148);
    caps_pass12<<<dim3(74, 2), 256, smem12>>>(X);
    caps_reduce<<<256, 256>>>(out, 1, 74);
    caps_pass12<<<dim3(74, 2), 256, smem12>>>(X);
    caps_reduce<<<256, 256>>>(out, 2, 74);
}

// round 15
// speedup vs baseline: 1.2423x; 1.0470x over previous
#include <cuda_runtime.h>

// Capsule dynamic routing. B=64, N=4096, I=8, C=32, D=16, 3 routing iters.
// prep_W: one-time interleave of W into g_Wil[n][r][c] (r=jp*4+i2; f4 = j-pair
//   values for i=2i2,2i2+1) enabling linear cp.async staging.
// caps_pass0: uniform coupling; 8 b/thread, 64 b/CTA; 148 CTAs x 26/28 n.
// caps_pass12: 4 b/thread, 32 b/CTA; grid (74,2) x 54/56 n; o hoisted to regs;
//   hat/logit/acc in fma.rn.f32x2; softmax 5-shfl (lane=c).
// Both passes: TRIPLE-buffered cp.async W staging (2 groups outstanding).
// caps_reduce: 256 CTAs, 8-way uneven chunk split + shfl merge + squash.

#define B_ 64
#define N_ 4096
#define C_ 32

using u64 = unsigned long long;

__device__ float4 g_Wil[(size_t)N_ * 1024];              // 64MB interleaved W
__device__ float g_part[(size_t)148 * B_ * C_ * 16];     // 19.4MB partials
__device__ float g_Ocum[B_ * C_ * 16];                   // cumulative outs

__device__ __forceinline__ u64 fma2(u64 a, u64 b, u64 c) {
    u64 d; asm("fma.rn.f32x2 %0,%1,%2,%3;" : "=l"(d) : "l"(a), "l"(b), "l"(c)); return d;
}
__device__ __forceinline__ u64 mul2(u64 a, u64 b) {
    u64 d; asm("mul.rn.f32x2 %0,%1,%2;" : "=l"(d) : "l"(a), "l"(b)); return d;
}
__device__ __forceinline__ u64 pack2(float x) {
    u64 d; asm("mov.b64 %0,{%1,%1};" : "=l"(d) : "f"(x)); return d;
}
__device__ __forceinline__ float hadd2(u64 v) {
    float a, b; asm("mov.b64 {%0,%1},%2;" : "=f"(a), "=f"(b) : "l"(v)); return a + b;
}
__device__ __forceinline__ float2 unpk(u64 v) {
    float a, b; asm("mov.b64 {%0,%1},%2;" : "=f"(a), "=f"(b) : "l"(v)); return make_float2(a, b);
}
__device__ __forceinline__ unsigned smem_u32(const void* p) {
    unsigned a; asm("{ .reg .u64 t; cvta.to.shared.u64 t, %1; cvt.u32.u64 %0, t; }" : "=r"(a) : "l"(p));
    return a;
}
__device__ __forceinline__ void cpa16(unsigned dst, const void* src) {
    asm volatile("cp.async.cg.shared.global [%0], [%1], 16;" :: "r"(dst), "l"(src));
}
__device__ __forceinline__ void cpa_commit() { asm volatile("cp.async.commit_group;"); }
__device__ __forceinline__ void cpa_wait2() { asm volatile("cp.async.wait_group 2;"); }
__device__ __forceinline__ void cpa_wait1() { asm volatile("cp.async.wait_group 1;"); }
__device__ __forceinline__ void cpa_wait0() { asm volatile("cp.async.wait_group 0;"); }

// ---------------- W interleave prepass: grid 4096 x 256 ----------------
__global__ void prep_W(const float* __restrict__ W) {
    const int tid = threadIdx.x;
    const int c = tid & 31, jp = tid >> 5;          // jp 0..7
    const int n = blockIdx.x;
    const float4* gp = reinterpret_cast<const float4*>(W)
                         + (((size_t)c * N_ + n) * 16 + 2 * jp) * 2;
    float4 A0 = gp[0], A1 = gp[1], B0 = gp[2], B1 = gp[3];  // rows j=2jp, 2jp+1
    float4* dst = g_Wil + (size_t)n * 1024 + (jp * 4) * 32 + c;
    dst[0]  = make_float4(A0.x, B0.x, A0.y, B0.y);   // i2=0
    dst[32] = make_float4(A0.z, B0.z, A0.w, B0.w);   // i2=1
    dst[64] = make_float4(A1.x, B1.x, A1.y, B1.y);   // i2=2
    dst[96] = make_float4(A1.z, B1.z, A1.w, B1.w);   // i2=3
}

__global__ void nop_k() {}   // window shifter: ncu -s5 lands on caps_pass0

// ---------------- pass 0: uniform coupling, 8 b/thread, 148 CTAs ----------------
// smem: sW 96KB (3 buf x 2 n) + sXp 112KB ([bl 64][n<=28 stride 224][i]) = 208KB.
__global__ void __launch_bounds__(256, 1)
caps_pass0(const float* __restrict__ X) {
    extern __shared__ char smraw[];
    float4* sW = reinterpret_cast<float4*>(smraw);               // 6144 f4
    u64* sXp = reinterpret_cast<u64*>(smraw + 98304);
    const int chunk = blockIdx.x;
    const int count = 13 + (chunk < 124 ? 1 : 0);                // 2n-units
    const int n0 = (chunk * 13 + min(chunk, 124)) * 2;
    const int tid = threadIdx.x, c = tid & 31, w = tid >> 5;
    const unsigned sWa = smem_u32(sW);

    // stage X as duplicated pairs (guarded: rem < 4*count f4 per bl)
    const int remMax = 4 * count;                                // <= 56
    for (int t = tid; t < 64 * 64; t += 256) {
        int bl = t >> 6, rem = t & 63;                           // rem = n*2+ih
        if (rem < remMax) {
            float4 v = reinterpret_cast<const float4*>(X)[(size_t)bl * 8192 + n0 * 2 + rem];
            u64* d = sXp + bl * 224 + (rem >> 1) * 8 + (rem & 1) * 4;
            d[0] = pack2(v.x); d[1] = pack2(v.y); d[2] = pack2(v.z); d[3] = pack2(v.w);
        }
    }

    u64 acc[8][8];
    #pragma unroll
    for (int bi = 0; bi < 8; ++bi)
        #pragma unroll
        for (int q = 0; q < 8; ++q) acc[bi][q] = 0ull;

    auto stage = [&](int sub) {                                  // buf = sub % 3
        const float4* src = g_Wil + (size_t)(n0 + sub * 2) * 1024;
        unsigned dst = sWa + (unsigned)((sub % 3) * 2048 + tid) * 16;
        #pragma unroll
        for (int k = 0; k < 8; ++k) cpa16(dst + k * 4096, src + tid + k * 256);
        cpa_commit();
    };
    stage(0);
    if (count > 1) stage(1);

    for (int sub = 0; sub < count; ++sub) {
        if (sub + 2 < count) { stage(sub + 2); cpa_wait2(); }
        else if (sub + 1 < count) cpa_wait1();
        else cpa_wait0();
        __syncthreads();
        const float4* Wb = sW + (sub % 3) * 2048;
        #pragma unroll
        for (int ln = 0; ln < 2; ++ln) {
            const float4* Wn = Wb + ln * 1024;
            const int nloc = sub * 2 + ln;
            #pragma unroll
            for (int q = 0; q < 4; ++q) {
                ulonglong2 Wq[8];
                #pragma unroll
                for (int k = 0; k < 8; ++k)
                    Wq[k] = reinterpret_cast<const ulonglong2*>(Wn + (q * 8 + k) * 32)[c];
                #pragma unroll
                for (int bi = 0; bi < 8; ++bi) {
                    const ulonglong2* xp = reinterpret_cast<const ulonglong2*>(
                        sXp + (w * 8 + bi) * 224 + nloc * 8);
                    ulonglong2 xA = xp[0], xB = xp[1], xC = xp[2], xD = xp[3];
                    u64 a0 = acc[bi][2 * q], a1 = acc[bi][2 * q + 1];
                    a0 = fma2(xA.x, Wq[0].x, a0); a0 = fma2(xA.y, Wq[0].y, a0);
                    a0 = fma2(xB.x, Wq[1].x, a0); a0 = fma2(xB.y, Wq[1].y, a0);
                    a0 = fma2(xC.x, Wq[2].x, a0); a0 = fma2(xC.y, Wq[2].y, a0);
                    a0 = fma2(xD.x, Wq[3].x, a0); a0 = fma2(xD.y, Wq[3].y, a0);
                    a1 = fma2(xA.x, Wq[4].x, a1); a1 = fma2(xA.y, Wq[4].y, a1);
                    a1 = fma2(xB.x, Wq[5].x, a1); a1 = fma2(xB.y, Wq[5].y, a1);
                    a1 = fma2(xC.x, Wq[6].x, a1); a1 = fma2(xC.y, Wq[6].y, a1);
                    a1 = fma2(xD.x, Wq[7].x, a1); a1 = fma2(xD.y, Wq[7].y, a1);
                    acc[bi][2 * q] = a0; acc[bi][2 * q + 1] = a1;
                }
            }
        }
        __syncthreads();
    }

    #pragma unroll
    for (int bi = 0; bi < 8; ++bi) {
        const int b = w * 8 + bi;
        float4* dst = reinterpret_cast<float4*>(g_part) + (((size_t)chunk * B_ + b) * C_ + c) * 4;
        #pragma unroll
        for (int qd = 0; qd < 4; ++qd) {
            float2 p0 = unpk(acc[bi][2 * qd]), p1 = unpk(acc[bi][2 * qd + 1]);
            dst[qd] = make_float4(p0.x * (1.f / 32.f), p0.y * (1.f / 32.f),
                                  p1.x * (1.f / 32.f), p1.y * (1.f / 32.f));
        }
    }
}

// ---------------- pass 1/2: 4 b/thread, o in regs, grid (74, 2) ----------------
// smem: sW 96KB (3 buf x 2 n) + sXp 112KB ([bl 32][n<=56 stride 448][i]) = 208KB.
__global__ void __launch_bounds__(256, 1)
caps_pass12(const float* __restrict__ X) {
    extern __shared__ char smraw[];
    float4* sW = reinterpret_cast<float4*>(smraw);
    u64* sXp = reinterpret_cast<u64*>(smraw + 98304);
    const int chunk = blockIdx.x, half = blockIdx.y;
    const int count = 27 + (chunk < 50 ? 1 : 0);                 // 2n-units
    const int n0 = (chunk * 27 + min(chunk, 50)) * 2;
    const int b0 = half * 32;
    const int tid = threadIdx.x, c = tid & 31, w = tid >> 5;
    const unsigned sWa = smem_u32(sW);

    const int remMax = 4 * count;                                // <= 112
    for (int t = tid; t < 32 * 128; t += 256) {
        int bl = t >> 7, rem = t & 127;
        if (rem < remMax) {
            float4 v = reinterpret_cast<const float4*>(X)[(size_t)(b0 + bl) * 8192 + n0 * 2 + rem];
            u64* d = sXp + bl * 448 + (rem >> 1) * 8 + (rem & 1) * 4;
            d[0] = pack2(v.x); d[1] = pack2(v.y); d[2] = pack2(v.z); d[3] = pack2(v.w);
        }
    }

    // hoist o (cumulative outs) to registers: loop-invariant over n
    u64 o2[4][8];
    #pragma unroll
    for (int bi = 0; bi < 4; ++bi) {
        const int b = b0 + w * 4 + bi;
        const ulonglong2* op = reinterpret_cast<const ulonglong2*>(g_Ocum + (b * C_ + c) * 16);
        #pragma unroll
        for (int qd = 0; qd < 4; ++qd) {
            ulonglong2 u = op[qd];
            o2[bi][2 * qd] = u.x; o2[bi][2 * qd + 1] = u.y;
        }
    }

    u64 acc[4][8];
    #pragma unroll
    for (int bi = 0; bi < 4; ++bi)
        #pragma unroll
        for (int jp = 0; jp < 8; ++jp) acc[bi][jp] = 0ull;

    auto stage = [&](int sub) {
        const float4* src = g_Wil + (size_t)(n0 + sub * 2) * 1024;
        unsigned dst = sWa + (unsigned)((sub % 3) * 2048 + tid) * 16;
        #pragma unroll
        for (int k = 0; k < 8; ++k) cpa16(dst + k * 4096, src + tid + k * 256);
        cpa_commit();
    };
    stage(0);
    if (count > 1) stage(1);

    for (int sub = 0; sub < count; ++sub) {
        if (sub + 2 < count) { stage(sub + 2); cpa_wait2(); }
        else if (sub + 1 < count) cpa_wait1();
        else cpa_wait0();
        __syncthreads();
        const float4* Wb = sW + (sub % 3) * 2048;
        #pragma unroll
        for (int ln = 0; ln < 2; ++ln) {
            const float4* Wn = Wb + ln * 1024;
            const int nloc = sub * 2 + ln;
            u64 hat[4][8];
            #pragma unroll
            for (int q = 0; q < 4; ++q) {
                ulonglong2 Wq[8];
                #pragma unroll
                for (int k = 0; k < 8; ++k)
                    Wq[k] = reinterpret_cast<const ulonglong2*>(Wn + (q * 8 + k) * 32)[c];
                #pragma unroll
                for (int bi = 0; bi < 4; ++bi) {
                    const ulonglong2* xp = reinterpret_cast<const ulonglong2*>(
                        sXp + (w * 4 + bi) * 448 + nloc * 8);
                    ulonglong2 xA = xp[0], xB = xp[1], xC = xp[2], xD = xp[3];
                    u64 h0 = mul2(xA.x, Wq[0].x);
                    h0 = fma2(xA.y, Wq[0].y, h0);
                    h0 = fma2(xB.x, Wq[1].x, h0); h0 = fma2(xB.y, Wq[1].y, h0);
                    h0 = fma2(xC.x, Wq[2].x, h0); h0 = fma2(xC.y, Wq[2].y, h0);
                    h0 = fma2(xD.x, Wq[3].x, h0); h0 = fma2(xD.y, Wq[3].y, h0);
                    u64 h1 = mul2(xA.x, Wq[4].x);
                    h1 = fma2(xA.y, Wq[4].y, h1);
                    h1 = fma2(xB.x, Wq[5].x, h1); h1 = fma2(xB.y, Wq[5].y, h1);
                    h1 = fma2(xC.x, Wq[6].x, h1); h1 = fma2(xC.y, Wq[6].y, h1);
                    h1 = fma2(xD.x, Wq[7].x, h1); h1 = fma2(xD.y, Wq[7].y, h1);
                    hat[bi][2 * q] = h0; hat[bi][2 * q + 1] = h1;
                }
            }
            #pragma unroll
            for (int bi = 0; bi < 4; ++bi) {
                u64 lg = mul2(hat[bi][0], o2[bi][0]);
                lg = fma2(hat[bi][1], o2[bi][1], lg);
                lg = fma2(hat[bi][2], o2[bi][2], lg); lg = fma2(hat[bi][3], o2[bi][3], lg);
                lg = fma2(hat[bi][4], o2[bi][4], lg); lg = fma2(hat[bi][5], o2[bi][5], lg);
                lg = fma2(hat[bi][6], o2[bi][6], lg); lg = fma2(hat[bi][7], o2[bi][7], lg);
                const float e = __expf(hadd2(lg));   // logits O(1): no max-sub needed
                float s = e;
                s += __shfl_xor_sync(0xffffffffu, s, 1);
                s += __shfl_xor_sync(0xffffffffu, s, 2);
                s += __shfl_xor_sync(0xffffffffu, s, 4);
                s += __shfl_xor_sync(0xffffffffu, s, 8);
                s += __shfl_xor_sync(0xffffffffu, s, 16);
                const u64 cf = pack2(__fdividef(e, s));
                #pragma unroll
                for (int jp = 0; jp < 8; ++jp)
                    acc[bi][jp] = fma2(cf, hat[bi][jp], acc[bi][jp]);
            }
        }
        __syncthreads();
    }

    #pragma unroll
    for (int bi = 0; bi < 4; ++bi) {
        const int b = b0 + w * 4 + bi;
        float4* dst = reinterpret_cast<float4*>(g_part) + (((size_t)chunk * B_ + b) * C_ + c) * 4;
        #pragma unroll
        for (int qd = 0; qd < 4; ++qd) {
            float2 p0 = unpk(acc[bi][2 * qd]), p1 = unpk(acc[bi][2 * qd + 1]);
            dst[qd] = make_float4(p0.x, p0.y, p1.x, p1.y);
        }
    }
}

// ---------------- reduce + squash: grid 256 x 256, uneven 8-way split ----------------
__global__ void caps_reduce(float* __restrict__ out, int mode, int nch) {
    const int gt = blockIdx.x * 256 + threadIdx.x;
    const int idx4 = gt >> 3, eighth = gt & 7;
    const int kc = nch >> 3, rem = nch & 7;
    const int kstart = eighth * kc + min(eighth, rem);
    const int kcount = kc + (eighth < rem ? 1 : 0);
    float4 a = make_float4(0.f, 0.f, 0.f, 0.f);
    const float4* gp = reinterpret_cast<const float4*>(g_part) + idx4;
    for (int k = 0; k < kcount; ++k) {
        float4 v = gp[(size_t)(kstart + k) * 8192];
        a.x += v.x; a.y += v.y; a.z += v.z; a.w += v.w;
    }
    #pragma unroll
    for (int m = 1; m <= 4; m <<= 1) {
        a.x += __shfl_xor_sync(0xffffffffu, a.x, m);
        a.y += __shfl_xor_sync(0xffffffffu, a.y, m);
        a.z += __shfl_xor_sync(0xffffffffu, a.z, m);
        a.w += __shfl_xor_sync(0xffffffffu, a.w, m);
    }
    float sq = a.x * a.x + a.y * a.y + a.z * a.z + a.w * a.w;
    sq += __shfl_xor_sync(0xffffffffu, sq, 8);
    sq += __shfl_xor_sync(0xffffffffu, sq, 16);
    const float f = sq / ((1.f + sq) * sqrtf(sq + 1e-7f));
    float4 v = make_float4(a.x * f, a.y * f, a.z * f, a.w * f);
    if (eighth == 0) {
        float4* oc = reinterpret_cast<float4*>(g_Ocum);
        if (mode == 0) {
            oc[idx4] = v;
        } else if (mode == 1) {
            float4 o = oc[idx4];
            o.x += v.x; o.y += v.y; o.z += v.z; o.w += v.w;
            oc[idx4] = o;
        } else {
            reinterpret_cast<float4*>(out)[idx4] = v;
        }
    }
}

extern "C" void kernel_launch(void* const* d_in, const int* in_sizes, int n_in,
                              void* d_out, int out_size) {
    const float* X = (const float*)d_in[0];
    const float* W = (const float*)d_in[1];
    if (n_in >= 2 && in_sizes[0] != B_ * N_ * 8) {
        X = (const float*)d_in[1];
        W = (const float*)d_in[0];
    }
    float* out = (float*)d_out;

    const int smem0  = 98304 + 114688;   // 212992 B
    const int smem12 = 98304 + 114688;   // 212992 B
    cudaFuncSetAttribute(caps_pass0,  cudaFuncAttributeMaxDynamicSharedMemorySize, smem0);
    cudaFuncSetAttribute(caps_pass12, cudaFuncAttributeMaxDynamicSharedMemorySize, smem12);

    nop_k<<<1, 32>>>();                  // shift ncu -s5 window onto caps_pass0
    nop_k<<<1, 32>>>();
    nop_k<<<1, 32>>>();
    nop_k<<<1, 32>>>();
    prep_W<<<N_, 256>>>(W);
    caps_pass0<<<148, 256, smem0>>>(X);
    caps_reduce<<<256, 256>>>(out, 0, 148);
    caps_pass12<<<dim3(74, 2), 256, smem12>>>(X);
    caps_reduce<<<256, 256>>>(out, 1, 74);
    caps_pass12<<<dim3(74, 2), 256, smem12>>>(X);
    caps_reduce<<<256, 256>>>(out, 2, 74);
}

// round 16
// speedup vs baseline: 1.2597x; 1.0140x over previous
#include <cuda_runtime.h>

// Capsule dynamic routing. B=64, N=4096, I=8, C=32, D=16, 3 routing iters.
// prep_W: one-time interleave of W into g_Wil[n][r][c] (r=jp*4+i2; f4 = j-pair
//   values for i=2i2,2i2+1) enabling linear cp.async staging.
// caps_pass0: uniform coupling; 8 b/thread, 64 b/CTA; 148 CTAs x 26/28 n.
// caps_pass12: 4 b/thread, 32 b/CTA; grid (74,2) x 54/56 n; o hoisted to regs;
//   hat/logit/acc in fma.rn.f32x2; softmax 5-shfl (lane=c).
// Both passes: TRIPLE-buffered cp.async W staging (2 groups outstanding).
// caps_reduce: 256 CTAs, 8-way uneven chunk split + shfl merge + squash.

#define B_ 64
#define N_ 4096
#define C_ 32

using u64 = unsigned long long;

__device__ float4 g_Wil[(size_t)N_ * 1024];              // 64MB interleaved W
__device__ float g_part[(size_t)148 * B_ * C_ * 16];     // 19.4MB partials
__device__ float g_Ocum[B_ * C_ * 16];                   // cumulative outs

__device__ __forceinline__ u64 fma2(u64 a, u64 b, u64 c) {
    u64 d; asm("fma.rn.f32x2 %0,%1,%2,%3;" : "=l"(d) : "l"(a), "l"(b), "l"(c)); return d;
}
__device__ __forceinline__ u64 mul2(u64 a, u64 b) {
    u64 d; asm("mul.rn.f32x2 %0,%1,%2;" : "=l"(d) : "l"(a), "l"(b)); return d;
}
__device__ __forceinline__ u64 pack2(float x) {
    u64 d; asm("mov.b64 %0,{%1,%1};" : "=l"(d) : "f"(x)); return d;
}
__device__ __forceinline__ float hadd2(u64 v) {
    float a, b; asm("mov.b64 {%0,%1},%2;" : "=f"(a), "=f"(b) : "l"(v)); return a + b;
}
__device__ __forceinline__ float2 unpk(u64 v) {
    float a, b; asm("mov.b64 {%0,%1},%2;" : "=f"(a), "=f"(b) : "l"(v)); return make_float2(a, b);
}
__device__ __forceinline__ unsigned smem_u32(const void* p) {
    unsigned a; asm("{ .reg .u64 t; cvta.to.shared.u64 t, %1; cvt.u32.u64 %0, t; }" : "=r"(a) : "l"(p));
    return a;
}
__device__ __forceinline__ void cpa16(unsigned dst, const void* src) {
    asm volatile("cp.async.cg.shared.global [%0], [%1], 16;" :: "r"(dst), "l"(src));
}
__device__ __forceinline__ void cpa_commit() { asm volatile("cp.async.commit_group;"); }
__device__ __forceinline__ void cpa_wait2() { asm volatile("cp.async.wait_group 2;"); }
__device__ __forceinline__ void cpa_wait1() { asm volatile("cp.async.wait_group 1;"); }
__device__ __forceinline__ void cpa_wait0() { asm volatile("cp.async.wait_group 0;"); }

// ---------------- W interleave prepass: grid 4096 x 256 ----------------
__global__ void prep_W(const float* __restrict__ W) {
    const int tid = threadIdx.x;
    const int c = tid & 31, jp = tid >> 5;          // jp 0..7
    const int n = blockIdx.x;
    const float4* gp = reinterpret_cast<const float4*>(W)
                         + (((size_t)c * N_ + n) * 16 + 2 * jp) * 2;
    float4 A0 = gp[0], A1 = gp[1], B0 = gp[2], B1 = gp[3];  // rows j=2jp, 2jp+1
    float4* dst = g_Wil + (size_t)n * 1024 + (jp * 4) * 32 + c;
    dst[0]  = make_float4(A0.x, B0.x, A0.y, B0.y);   // i2=0
    dst[32] = make_float4(A0.z, B0.z, A0.w, B0.w);   // i2=1
    dst[64] = make_float4(A1.x, B1.x, A1.y, B1.y);   // i2=2
    dst[96] = make_float4(A1.z, B1.z, A1.w, B1.w);   // i2=3
}

// ---------------- pass 0: uniform coupling, 8 b/thread, 148 CTAs ----------------
// smem: sW 96KB (3 buf x 2 n) + sXp 112KB ([bl 64][n<=28 stride 224][i]) = 208KB.
__global__ void __launch_bounds__(256, 1)
caps_pass0(const float* __restrict__ X) {
    extern __shared__ char smraw[];
    float4* sW = reinterpret_cast<float4*>(smraw);               // 6144 f4
    u64* sXp = reinterpret_cast<u64*>(smraw + 98304);
    const int chunk = blockIdx.x;
    const int count = 13 + (chunk < 124 ? 1 : 0);                // 2n-units
    const int n0 = (chunk * 13 + min(chunk, 124)) * 2;
    const int tid = threadIdx.x, c = tid & 31, w = tid >> 5;
    const unsigned sWa = smem_u32(sW);

    // stage X as duplicated pairs (guarded: rem < 4*count f4 per bl)
    const int remMax = 4 * count;                                // <= 56
    for (int t = tid; t < 64 * 64; t += 256) {
        int bl = t >> 6, rem = t & 63;                           // rem = n*2+ih
        if (rem < remMax) {
            float4 v = reinterpret_cast<const float4*>(X)[(size_t)bl * 8192 + n0 * 2 + rem];
            u64* d = sXp + bl * 224 + (rem >> 1) * 8 + (rem & 1) * 4;
            d[0] = pack2(v.x); d[1] = pack2(v.y); d[2] = pack2(v.z); d[3] = pack2(v.w);
        }
    }

    u64 acc[8][8];
    #pragma unroll
    for (int bi = 0; bi < 8; ++bi)
        #pragma unroll
        for (int q = 0; q < 8; ++q) acc[bi][q] = 0ull;

    auto stage = [&](int sub) {                                  // buf = sub % 3
        const float4* src = g_Wil + (size_t)(n0 + sub * 2) * 1024;
        unsigned dst = sWa + (unsigned)((sub % 3) * 2048 + tid) * 16;
        #pragma unroll
        for (int k = 0; k < 8; ++k) cpa16(dst + k * 4096, src + tid + k * 256);
        cpa_commit();
    };
    stage(0);
    if (count > 1) stage(1);

    for (int sub = 0; sub < count; ++sub) {
        if (sub + 2 < count) { stage(sub + 2); cpa_wait2(); }
        else if (sub + 1 < count) cpa_wait1();
        else cpa_wait0();
        __syncthreads();
        const float4* Wb = sW + (sub % 3) * 2048;
        #pragma unroll
        for (int ln = 0; ln < 2; ++ln) {
            const float4* Wn = Wb + ln * 1024;
            const int nloc = sub * 2 + ln;
            #pragma unroll
            for (int q = 0; q < 4; ++q) {
                ulonglong2 Wq[8];
                #pragma unroll
                for (int k = 0; k < 8; ++k)
                    Wq[k] = reinterpret_cast<const ulonglong2*>(Wn + (q * 8 + k) * 32)[c];
                #pragma unroll
                for (int bi = 0; bi < 8; ++bi) {
                    const ulonglong2* xp = reinterpret_cast<const ulonglong2*>(
                        sXp + (w * 8 + bi) * 224 + nloc * 8);
                    ulonglong2 xA = xp[0], xB = xp[1], xC = xp[2], xD = xp[3];
                    u64 a0 = acc[bi][2 * q], a1 = acc[bi][2 * q + 1];
                    a0 = fma2(xA.x, Wq[0].x, a0); a0 = fma2(xA.y, Wq[0].y, a0);
                    a0 = fma2(xB.x, Wq[1].x, a0); a0 = fma2(xB.y, Wq[1].y, a0);
                    a0 = fma2(xC.x, Wq[2].x, a0); a0 = fma2(xC.y, Wq[2].y, a0);
                    a0 = fma2(xD.x, Wq[3].x, a0); a0 = fma2(xD.y, Wq[3].y, a0);
                    a1 = fma2(xA.x, Wq[4].x, a1); a1 = fma2(xA.y, Wq[4].y, a1);
                    a1 = fma2(xB.x, Wq[5].x, a1); a1 = fma2(xB.y, Wq[5].y, a1);
                    a1 = fma2(xC.x, Wq[6].x, a1); a1 = fma2(xC.y, Wq[6].y, a1);
                    a1 = fma2(xD.x, Wq[7].x, a1); a1 = fma2(xD.y, Wq[7].y, a1);
                    acc[bi][2 * q] = a0; acc[bi][2 * q + 1] = a1;
                }
            }
        }
        __syncthreads();
    }

    #pragma unroll
    for (int bi = 0; bi < 8; ++bi) {
        const int b = w * 8 + bi;
        float4* dst = reinterpret_cast<float4*>(g_part) + (((size_t)chunk * B_ + b) * C_ + c) * 4;
        #pragma unroll
        for (int qd = 0; qd < 4; ++qd) {
            float2 p0 = unpk(acc[bi][2 * qd]), p1 = unpk(acc[bi][2 * qd + 1]);
            dst[qd] = make_float4(p0.x * (1.f / 32.f), p0.y * (1.f / 32.f),
                                  p1.x * (1.f / 32.f), p1.y * (1.f / 32.f));
        }
    }
}

// ---------------- pass 1/2: 4 b/thread, o in regs, grid (74, 2) ----------------
// smem: sW 96KB (3 buf x 2 n) + sXp 112KB ([bl 32][n<=56 stride 448][i]) = 208KB.
__global__ void __launch_bounds__(256, 1)
caps_pass12(const float* __restrict__ X) {
    extern __shared__ char smraw[];
    float4* sW = reinterpret_cast<float4*>(smraw);
    u64* sXp = reinterpret_cast<u64*>(smraw + 98304);
    const int chunk = blockIdx.x, half = blockIdx.y;
    const int count = 27 + (chunk < 50 ? 1 : 0);                 // 2n-units
    const int n0 = (chunk * 27 + min(chunk, 50)) * 2;
    const int b0 = half * 32;
    const int tid = threadIdx.x, c = tid & 31, w = tid >> 5;
    const unsigned sWa = smem_u32(sW);

    const int remMax = 4 * count;                                // <= 112
    for (int t = tid; t < 32 * 128; t += 256) {
        int bl = t >> 7, rem = t & 127;
        if (rem < remMax) {
            float4 v = reinterpret_cast<const float4*>(X)[(size_t)(b0 + bl) * 8192 + n0 * 2 + rem];
            u64* d = sXp + bl * 448 + (rem >> 1) * 8 + (rem & 1) * 4;
            d[0] = pack2(v.x); d[1] = pack2(v.y); d[2] = pack2(v.z); d[3] = pack2(v.w);
        }
    }

    // hoist o (cumulative outs) to registers: loop-invariant over n
    u64 o2[4][8];
    #pragma unroll
    for (int bi = 0; bi < 4; ++bi) {
        const int b = b0 + w * 4 + bi;
        const ulonglong2* op = reinterpret_cast<const ulonglong2*>(g_Ocum + (b * C_ + c) * 16);
        #pragma unroll
        for (int qd = 0; qd < 4; ++qd) {
            ulonglong2 u = op[qd];
            o2[bi][2 * qd] = u.x; o2[bi][2 * qd + 1] = u.y;
        }
    }

    u64 acc[4][8];
    #pragma unroll
    for (int bi = 0; bi < 4; ++bi)
        #pragma unroll
        for (int jp = 0; jp < 8; ++jp) acc[bi][jp] = 0ull;

    auto stage = [&](int sub) {
        const float4* src = g_Wil + (size_t)(n0 + sub * 2) * 1024;
        unsigned dst = sWa + (unsigned)((sub % 3) * 2048 + tid) * 16;
        #pragma unroll
        for (int k = 0; k < 8; ++k) cpa16(dst + k * 4096, src + tid + k * 256);
        cpa_commit();
    };
    stage(0);
    if (count > 1) stage(1);

    for (int sub = 0; sub < count; ++sub) {
        if (sub + 2 < count) { stage(sub + 2); cpa_wait2(); }
        else if (sub + 1 < count) cpa_wait1();
        else cpa_wait0();
        __syncthreads();
        const float4* Wb = sW + (sub % 3) * 2048;
        #pragma unroll
        for (int ln = 0; ln < 2; ++ln) {
            const float4* Wn = Wb + ln * 1024;
            const int nloc = sub * 2 + ln;
            u64 hat[4][8];
            #pragma unroll
            for (int q = 0; q < 4; ++q) {
                ulonglong2 Wq[8];
                #pragma unroll
                for (int k = 0; k < 8; ++k)
                    Wq[k] = reinterpret_cast<const ulonglong2*>(Wn + (q * 8 + k) * 32)[c];
                #pragma unroll
                for (int bi = 0; bi < 4; ++bi) {
                    const ulonglong2* xp = reinterpret_cast<const ulonglong2*>(
                        sXp + (w * 4 + bi) * 448 + nloc * 8);
                    ulonglong2 xA = xp[0], xB = xp[1], xC = xp[2], xD = xp[3];
                    u64 h0 = mul2(xA.x, Wq[0].x);
                    h0 = fma2(xA.y, Wq[0].y, h0);
                    h0 = fma2(xB.x, Wq[1].x, h0); h0 = fma2(xB.y, Wq[1].y, h0);
                    h0 = fma2(xC.x, Wq[2].x, h0); h0 = fma2(xC.y, Wq[2].y, h0);
                    h0 = fma2(xD.x, Wq[3].x, h0); h0 = fma2(xD.y, Wq[3].y, h0);
                    u64 h1 = mul2(xA.x, Wq[4].x);
                    h1 = fma2(xA.y, Wq[4].y, h1);
                    h1 = fma2(xB.x, Wq[5].x, h1); h1 = fma2(xB.y, Wq[5].y, h1);
                    h1 = fma2(xC.x, Wq[6].x, h1); h1 = fma2(xC.y, Wq[6].y, h1);
                    h1 = fma2(xD.x, Wq[7].x, h1); h1 = fma2(xD.y, Wq[7].y, h1);
                    hat[bi][2 * q] = h0; hat[bi][2 * q + 1] = h1;
                }
            }
            #pragma unroll
            for (int bi = 0; bi < 4; ++bi) {
                u64 lg = mul2(hat[bi][0], o2[bi][0]);
                lg = fma2(hat[bi][1], o2[bi][1], lg);
                lg = fma2(hat[bi][2], o2[bi][2], lg); lg = fma2(hat[bi][3], o2[bi][3], lg);
                lg = fma2(hat[bi][4], o2[bi][4], lg); lg = fma2(hat[bi][5], o2[bi][5], lg);
                lg = fma2(hat[bi][6], o2[bi][6], lg); lg = fma2(hat[bi][7], o2[bi][7], lg);
                const float e = __expf(hadd2(lg));   // logits O(1): no max-sub needed
                float s = e;
                s += __shfl_xor_sync(0xffffffffu, s, 1);
                s += __shfl_xor_sync(0xffffffffu, s, 2);
                s += __shfl_xor_sync(0xffffffffu, s, 4);
                s += __shfl_xor_sync(0xffffffffu, s, 8);
                s += __shfl_xor_sync(0xffffffffu, s, 16);
                const u64 cf = pack2(__fdividef(e, s));
                #pragma unroll
                for (int jp = 0; jp < 8; ++jp)
                    acc[bi][jp] = fma2(cf, hat[bi][jp], acc[bi][jp]);
            }
        }
        __syncthreads();
    }

    #pragma unroll
    for (int bi = 0; bi < 4; ++bi) {
        const int b = b0 + w * 4 + bi;
        float4* dst = reinterpret_cast<float4*>(g_part) + (((size_t)chunk * B_ + b) * C_ + c) * 4;
        #pragma unroll
        for (int qd = 0; qd < 4; ++qd) {
            float2 p0 = unpk(acc[bi][2 * qd]), p1 = unpk(acc[bi][2 * qd + 1]);
            dst[qd] = make_float4(p0.x, p0.y, p1.x, p1.y);
        }
    }
}

// ---------------- reduce + squash: grid 256 x 256, uneven 8-way split ----------------
__global__ void caps_reduce(float* __restrict__ out, int mode, int nch) {
    const int gt = blockIdx.x * 256 + threadIdx.x;
    const int idx4 = gt >> 3, eighth = gt & 7;
    const int kc = nch >> 3, rem = nch & 7;
    const int kstart = eighth * kc + min(eighth, rem);
    const int kcount = kc + (eighth < rem ? 1 : 0);
    float4 a = make_float4(0.f, 0.f, 0.f, 0.f);
    const float4* gp = reinterpret_cast<const float4*>(g_part) + idx4;
    for (int k = 0; k < kcount; ++k) {
        float4 v = gp[(size_t)(kstart + k) * 8192];
        a.x += v.x; a.y += v.y; a.z += v.z; a.w += v.w;
    }
    #pragma unroll
    for (int m = 1; m <= 4; m <<= 1) {
        a.x += __shfl_xor_sync(0xffffffffu, a.x, m);
        a.y += __shfl_xor_sync(0xffffffffu, a.y, m);
        a.z += __shfl_xor_sync(0xffffffffu, a.z, m);
        a.w += __shfl_xor_sync(0xffffffffu, a.w, m);
    }
    float sq = a.x * a.x + a.y * a.y + a.z * a.z + a.w * a.w;
    sq += __shfl_xor_sync(0xffffffffu, sq, 8);
    sq += __shfl_xor_sync(0xffffffffu, sq, 16);
    const float f = sq / ((1.f + sq) * sqrtf(sq + 1e-7f));
    float4 v = make_float4(a.x * f, a.y * f, a.z * f, a.w * f);
    if (eighth == 0) {
        float4* oc = reinterpret_cast<float4*>(g_Ocum);
        if (mode == 0) {
            oc[idx4] = v;
        } else if (mode == 1) {
            float4 o = oc[idx4];
            o.x += v.x; o.y += v.y; o.z += v.z; o.w += v.w;
            oc[idx4] = o;
        } else {
            reinterpret_cast<float4*>(out)[idx4] = v;
        }
    }
}

extern "C" void kernel_launch(void* const* d_in, const int* in_sizes, int n_in,
                              void* d_out, int out_size) {
    const float* X = (const float*)d_in[0];
    const float* W = (const float*)d_in[1];
    if (n_in >= 2 && in_sizes[0] != B_ * N_ * 8) {
        X = (const float*)d_in[1];
        W = (const float*)d_in[0];
    }
    float* out = (float*)d_out;

    const int smem0  = 98304 + 114688;   // 212992 B
    const int smem12 = 98304 + 114688;   // 212992 B
    cudaFuncSetAttribute(caps_pass0,  cudaFuncAttributeMaxDynamicSharedMemorySize, smem0);
    cudaFuncSetAttribute(caps_pass12, cudaFuncAttributeMaxDynamicSharedMemorySize, smem12);

    prep_W<<<N_, 256>>>(W);
    caps_pass0<<<148, 256, smem0>>>(X);
    caps_reduce<<<256, 256>>>(out, 0, 148);
    caps_pass12<<<dim3(74, 2), 256, smem12>>>(X);
    caps_reduce<<<256, 256>>>(out, 1, 74);
    caps_pass12<<<dim3(74, 2), 256, smem12>>>(X);
    caps_reduce<<<256, 256>>>(out, 2, 74);
}